// round 8
// baseline (speedup 1.0000x reference)
#include <cuda_runtime.h>
#include <math.h>
#include <stdint.h>

#define DDIM   256
#define BATCH  128
#define SEQ    1024
#define NROWS  (BATCH*SEQ)          // 131072
#define RT     16                   // rows per tile
#define TSTRIDE 264                 // floats per smem tile row (256 + 8 pad)
#define NBLK_B 2048
#define TPB_B  (NROWS/(RT*NBLK_B))  // 4 tiles per block
#define NBLK_C 2048
#define TPB_C  (NROWS/(RT*NBLK_C))  // 4

// ---- scratch (static device globals; no allocation) ----
__device__ __align__(16) float g_part[8*BATCH*DDIM];
__device__ __align__(16) float g_cb[BATCH*DDIM];
__device__ __align__(16) float g_mean[DDIM];
__device__ float g_ic;
__device__ __align__(16) float g_bpS[NBLK_B*DDIM];
__device__ __align__(16) float g_bpQ[NBLK_B*DDIM];
__device__ __align__(16) float g_scale[DDIM];
__device__ float g_ib;
__device__ float g_lab;
__device__ __align__(16) float4 g_rowsc[NROWS];   // per-row (f, gc, c, 0)

__device__ __forceinline__ float warpsum(float v) {
    #pragma unroll
    for (int off = 16; off > 0; off >>= 1)
        v += __shfl_xor_sync(0xffffffffu, v, off);
    return v;
}
__device__ __forceinline__ void warpsum2(float& a, float& b) {
    #pragma unroll
    for (int off = 16; off > 0; off >>= 1) {
        a += __shfl_xor_sync(0xffffffffu, a, off);
        b += __shfl_xor_sync(0xffffffffu, b, off);
    }
}
__device__ __forceinline__ float blocksum256(float v, float* sh) {
    const int lane = threadIdx.x & 31;
    const int warp = threadIdx.x >> 5;
    float w = warpsum(v);
    if (lane == 0) sh[warp] = w;
    __syncthreads();
    float r = sh[0];
    #pragma unroll
    for (int i = 1; i < 8; i++) r += sh[i];
    return r;
}
__device__ __forceinline__ float acosh_over_s(float alpha) {
    float a2m1 = fmaf(alpha, alpha, -1.0f);
    float r = rsqrtf(a2m1);
    float s = a2m1 * r;
    return __logf(alpha + s) * r;
}
__device__ __forceinline__ void cpasync16(float* smem, const float4* gmem) {
    uint32_t s = (uint32_t)__cvta_generic_to_shared(smem);
    asm volatile("cp.async.cg.shared.global [%0], [%1], 16;" :: "r"(s), "l"(gmem));
}
__device__ __forceinline__ void cpcommit() { asm volatile("cp.async.commit_group;"); }
template<int N> __device__ __forceinline__ void cpwait() {
    asm volatile("cp.async.wait_group %0;" :: "n"(N));
}

// ---------------------------------------------------------------------------
// Pass A: per-(chunk j, batch b) feature sums over 128 rows of S.
// ---------------------------------------------------------------------------
__global__ void __launch_bounds__(256) passA_kernel(const float* __restrict__ x) {
    const int j = blockIdx.x;
    const int b = blockIdx.y;
    const int d = threadIdx.x;
    const float* p = x + ((size_t)b*SEQ + (size_t)j*128) * DDIM + d;
    float a0=0.f,a1=0.f,a2=0.f,a3=0.f,a4=0.f,a5=0.f,a6=0.f,a7=0.f;
    #pragma unroll 2
    for (int s = 0; s < 128; s += 8) {
        a0 += p[(s+0)*DDIM]; a1 += p[(s+1)*DDIM];
        a2 += p[(s+2)*DDIM]; a3 += p[(s+3)*DDIM];
        a4 += p[(s+4)*DDIM]; a5 += p[(s+5)*DDIM];
        a6 += p[(s+6)*DDIM]; a7 += p[(s+7)*DDIM];
    }
    g_part[((size_t)(j*BATCH + b))*DDIM + d] = ((a0+a1)+(a2+a3)) + ((a4+a5)+(a6+a7));
}

// ---------------------------------------------------------------------------
__global__ void __launch_bounds__(256) a2a_kernel() {
    __shared__ float sh[8];
    const int b = blockIdx.x;
    const int d = threadIdx.x;
    float a = 0.f;
    #pragma unroll
    for (int j = 0; j < 8; j++)
        a += g_part[(size_t)(j*BATCH + b)*DDIM + d];
    a *= (1.0f / (float)SEQ);
    float p = (d == 0) ? -a*a : a*a;
    float l = blocksum256(p, sh);
    float dn = rsqrtf(fmaxf(fabsf(l), 1e-8f));
    g_cb[(size_t)b*DDIM + d] = a * dn;
}

__global__ void __launch_bounds__(256) a2b_kernel() {
    __shared__ float sh[8];
    const int d = threadIdx.x;
    float a = 0.f;
    #pragma unroll 8
    for (int b = 0; b < BATCH; b++) a += g_cb[(size_t)b*DDIM + d];
    a *= (1.0f / (float)BATCH);
    float p = (d == 0) ? -a*a : a*a;
    float l = blocksum256(p, sh);
    float dn = rsqrtf(fmaxf(fabsf(l), 1e-8f));
    float mv = a * dn;
    g_mean[d] = mv;
    if (d == 0) g_ic = 1.0f / (1.0f + mv);
}

// ---------------------------------------------------------------------------
// Pass B (tiled): block stages 16-row tiles in smem (cp.async double buffer).
//  P1: 16 rows x 16 segs partial dots.  P2: 16 threads finish row scalars
//  (f, gc, c) and store g_rowsc.  P3: thread-per-feature stat accumulation.
// ---------------------------------------------------------------------------
__global__ void __launch_bounds__(256) passB_kernel(const float* __restrict__ x) {
    __shared__ __align__(16) float tile[2][RT*TSTRIDE];
    __shared__ float ps[RT][17];
    __shared__ float rs[RT][4];
    __shared__ __align__(16) float ms[DDIM];
    const int tid = threadIdx.x;
    const int pr  = tid >> 4;
    const int psg = tid & 15;

    if (tid < 64)
        reinterpret_cast<float4*>(ms)[tid] = reinterpret_cast<const float4*>(g_mean)[tid];
    const float mdv = g_mean[tid];
    const float m0_ = g_mean[0];
    const float ic_ = g_ic;

    const int t0 = blockIdx.x * TPB_B;
    auto issue = [&](int t, int stg) {
        const float4* src = reinterpret_cast<const float4*>(x) + (size_t)(t0 + t) * (RT*64);
        #pragma unroll
        for (int k = 0; k < 4; k++) {
            int i = tid + (k << 8);
            int row = i >> 6, col4 = i & 63;
            cpasync16(&tile[stg][row*TSTRIDE + (col4<<2)], src + i);
        }
    };
    issue(0, 0); cpcommit();
    issue(1, 1); cpcommit();

    float smv = 0.f, sqv = 0.f;

    for (int j = 0; j < TPB_B; j++) {
        const int cur = j & 1;
        const int rowbase = (t0 + j) * RT;
        cpwait<1>();
        __syncthreads();                       // tile[cur] visible

        // P1: partial dots (strided feature access, conflict-light)
        {
            const float* tp = &tile[cur][pr*TSTRIDE];
            float acc = 0.f;
            #pragma unroll
            for (int k = 0; k < 16; k++) {
                int fidx = psg + (k << 4);
                acc += tp[fidx] * ms[fidx];
            }
            if (psg == 0) acc -= 2.0f * tp[0] * ms[0];
            ps[pr][psg] = acc;
        }
        __syncthreads();

        // P2: row scalars
        if (tid < 16) {
            float l = 0.f;
            #pragma unroll
            for (int k = 0; k < 16; k++) l += ps[tid][k];
            float alpha = fmaxf(-l, 1.0f + 1e-7f);
            float x0 = tile[cur][tid*TSTRIDE];
            float f  = acosh_over_s(alpha);
            float c  = f * (x0 - alpha*m0_) * ic_;
            float gc = fmaf(f, alpha, c);
            rs[tid][0] = f; rs[tid][1] = gc; rs[tid][2] = c;
            g_rowsc[rowbase + tid] = make_float4(f, gc, c, 0.f);
        }
        __syncthreads();

        // P3: per-feature stats (column access, conflict-free)
        {
            #pragma unroll
            for (int r = 0; r < RT; r++) {
                float f  = rs[r][0];
                float gc = rs[r][1];
                float xv = tile[cur][r*TSTRIDE + tid];
                float t  = fmaf(f, xv, -gc*mdv);
                if (tid == 0) t -= rs[r][2];
                smv += t;
                sqv += t*t;
            }
        }
        __syncthreads();                       // done reading tile[cur]
        if (j + 2 < TPB_B) issue(j + 2, cur);
        cpcommit();
    }

    g_bpS[(size_t)blockIdx.x*DDIM + tid] = smv;
    g_bpQ[(size_t)blockIdx.x*DDIM + tid] = sqv;
}

// ---------------------------------------------------------------------------
__global__ void __launch_bounds__(256) finB_kernel(const float* __restrict__ beta,
                                                   const float* __restrict__ gamma) {
    __shared__ float shS[8];
    __shared__ float shQ[8];
    const int d   = blockIdx.x;
    const int tid = threadIdx.x;
    const int lane = tid & 31;
    const int warp = tid >> 5;

    float s = 0.f, q = 0.f;
    #pragma unroll
    for (int i = 0; i < NBLK_B/256; i++) {
        int b = i*256 + tid;
        s += g_bpS[(size_t)b*DDIM + d];
        q += g_bpQ[(size_t)b*DDIM + d];
    }
    warpsum2(s, q);
    if (lane == 0) { shS[warp] = s; shQ[warp] = q; }
    __syncthreads();
    if (tid == 0) {
        float S = shS[0], Q = shQ[0];
        #pragma unroll
        for (int i = 1; i < 8; i++) { S += shS[i]; Q += shQ[i]; }
        const float invN = 1.0f / (float)NROWS;
        float mu  = S * invN;
        float var = Q * invN - mu*mu;
        g_scale[d] = gamma[0] * rsqrtf(var + 1e-5f);
        if (d == 0) {
            float b0 = beta[0];
            g_ib  = 1.0f / (1.0f + b0);
            g_lab = -2.0f * (1.0f + b0);
        }
    }
}

// ---------------------------------------------------------------------------
// Pass C (tiled): reuses g_rowsc (no dot phase).
//  P1: partial q=linner(beta,w), n=linner(w,w).  P2: 16 threads -> cb,ch,sh.
//  P3: thread-per-feature output store.
// ---------------------------------------------------------------------------
__global__ void __launch_bounds__(256) passC_kernel(const float* __restrict__ x,
                                                    const float* __restrict__ beta,
                                                    float* __restrict__ out) {
    __shared__ __align__(16) float tile[2][RT*TSTRIDE];
    __shared__ float psq[RT][17];
    __shared__ float psn[RT][17];
    __shared__ float rs_s[2][RT][4];           // f, gc, c per row (double-buffered)
    __shared__ float rs2[RT][4];               // cb, ch, sh per row
    __shared__ __align__(16) float ms[DDIM];
    __shared__ __align__(16) float scs[DDIM];
    __shared__ __align__(16) float bts[DDIM];
    const int tid = threadIdx.x;
    const int pr  = tid >> 4;
    const int psg = tid & 15;

    if (tid < 64) {
        reinterpret_cast<float4*>(ms)[tid]  = reinterpret_cast<const float4*>(g_mean)[tid];
        reinterpret_cast<float4*>(scs)[tid] = reinterpret_cast<const float4*>(g_scale)[tid];
        reinterpret_cast<float4*>(bts)[tid] = reinterpret_cast<const float4*>(beta)[tid];
    }
    const float mdv = g_mean[tid];
    const float scd = g_scale[tid];
    const float btd = beta[tid];
    const float ib  = g_ib;
    const float lab = g_lab;

    const int t0 = blockIdx.x * TPB_C;
    auto issue = [&](int t, int stg) {
        const float4* src = reinterpret_cast<const float4*>(x) + (size_t)(t0 + t) * (RT*64);
        #pragma unroll
        for (int k = 0; k < 4; k++) {
            int i = tid + (k << 8);
            int row = i >> 6, col4 = i & 63;
            cpasync16(&tile[stg][row*TSTRIDE + (col4<<2)], src + i);
        }
    };
    issue(0, 0); cpcommit();
    issue(1, 1); cpcommit();
    if (tid < 16) {
        float4 v = __ldg(&g_rowsc[(size_t)t0*RT + tid]);
        rs_s[0][tid][0] = v.x; rs_s[0][tid][1] = v.y; rs_s[0][tid][2] = v.z;
    }

    for (int j = 0; j < TPB_C; j++) {
        const int cur = j & 1;
        const int rowbase = (t0 + j) * RT;
        cpwait<1>();
        __syncthreads();                       // tile[cur] + rs_s[cur] visible

        // prefetch next tile's row scalars
        float4 pre = make_float4(0.f,0.f,0.f,0.f);
        if (tid < 16 && j + 1 < TPB_C)
            pre = __ldg(&g_rowsc[(size_t)(rowbase + RT) + tid]);

        // P1: partial q, n
        {
            const float* tp = &tile[cur][pr*TSTRIDE];
            const float f  = rs_s[cur][pr][0];
            const float gc = rs_s[cur][pr][1];
            const float c  = rs_s[cur][pr][2];
            float qa = 0.f, na = 0.f;
            #pragma unroll
            for (int k = 0; k < 16; k++) {
                int fidx = psg + (k << 4);
                float xv = tp[fidx];
                float t  = fmaf(f, xv, -gc*ms[fidx]);
                if (psg == 0 && k == 0) {
                    float w = (t - c) * scs[0];
                    qa -= bts[0]*w;  na -= w*w;
                } else {
                    float w = t * scs[fidx];
                    qa = fmaf(bts[fidx], w, qa);
                    na = fmaf(w, w, na);
                }
            }
            psq[pr][psg] = qa;
            psn[pr][psg] = na;
        }
        __syncthreads();

        // P2: per-row epilogue scalars
        if (tid < 16) {
            float q = 0.f, n = 0.f;
            #pragma unroll
            for (int k = 0; k < 16; k++) { q += psq[tid][k]; n += psn[tid][k]; }
            float f  = rs_s[cur][tid][0];
            float gc = rs_s[cur][tid][1];
            float c  = rs_s[cur][tid][2];
            float x0 = tile[cur][tid*TSTRIDE];
            float w0 = (fmaf(f, x0, -gc*ms[0]) - c) * scs[0];
            float cb = q * ib;
            float nn2 = n + 2.0f*cb*(q - w0) + cb*cb*lab;
            float nn = sqrtf(fmaxf(nn2, 1e-7f));
            float e  = __expf(nn);
            float ei = __frcp_rn(e);
            rs2[tid][0] = cb;
            rs2[tid][1] = 0.5f*(e + ei);
            rs2[tid][2] = 0.5f*(e - ei) * __frcp_rn(nn);
        }
        __syncthreads();

        // stash prefetched scalars into other stage
        if (tid < 16 && j + 1 < TPB_C) {
            rs_s[1-cur][tid][0] = pre.x;
            rs_s[1-cur][tid][1] = pre.y;
            rs_s[1-cur][tid][2] = pre.z;
        }

        // P3: per-feature output
        {
            float* op = out + (size_t)rowbase * DDIM + tid;
            #pragma unroll
            for (int r = 0; r < RT; r++) {
                float f  = rs_s[cur][r][0];
                float gc = rs_s[cur][r][1];
                float cb = rs2[r][0];
                float ch = rs2[r][1];
                float sh = rs2[r][2];
                float xv = tile[cur][r*TSTRIDE + tid];
                float t  = fmaf(f, xv, -gc*mdv);
                if (tid == 0) t -= rs_s[cur][r][2];
                float w  = t * scd;
                float o  = fmaf(ch, btd, sh * fmaf(cb, btd, w));
                if (tid == 0) o += sh * cb;
                __stcs(op + (size_t)r * DDIM, o);
            }
        }
        __syncthreads();                       // done reading tile[cur]
        if (j + 2 < TPB_C) issue(j + 2, cur);
        cpcommit();
    }
}

// ---------------------------------------------------------------------------
extern "C" void kernel_launch(void* const* d_in, const int* in_sizes, int n_in,
                              void* d_out, int out_size) {
    const float* x     = (const float*)d_in[0];
    const float* beta  = (const float*)d_in[1];
    const float* gamma = (const float*)d_in[2];
    float* out = (float*)d_out;

    dim3 gA(8, BATCH);
    passA_kernel<<<gA, 256>>>(x);
    a2a_kernel<<<BATCH, 256>>>();
    a2b_kernel<<<1, 256>>>();
    passB_kernel<<<NBLK_B, 256>>>(x);
    finB_kernel<<<DDIM, 256>>>(beta, gamma);
    passC_kernel<<<NBLK_C, 256>>>(x, beta, out);
}

// round 10
// speedup vs baseline: 1.1692x; 1.1692x over previous
#include <cuda_runtime.h>
#include <math.h>

#define DDIM   256
#define BATCH  128
#define SEQ    1024
#define NROWS  (BATCH*SEQ)          // 131072
#define HALF   (NROWS/2)            // 65536
#define NBLK_B 512
#define NBLK_C 2048

// ---- scratch (static device globals; no allocation) ----
__device__ __align__(16) float g_part[8*BATCH*DDIM];
__device__ __align__(16) float g_cb[BATCH*DDIM];
__device__ __align__(16) float g_mean[DDIM];
__device__ float g_ic;
__device__ __align__(16) float g_bpS[NBLK_B*DDIM];
__device__ __align__(16) float g_bpQ[NBLK_B*DDIM];
__device__ __align__(16) float g_scale[DDIM];
__device__ float g_ib;
__device__ float g_lab;
__device__ __align__(16) float4 g_rowsc[NROWS];   // per-row (f, gc, c, 0)

__device__ __forceinline__ float warpsum(float v) {
    #pragma unroll
    for (int off = 16; off > 0; off >>= 1)
        v += __shfl_xor_sync(0xffffffffu, v, off);
    return v;
}
__device__ __forceinline__ void warpsum2(float& a, float& b) {
    #pragma unroll
    for (int off = 16; off > 0; off >>= 1) {
        a += __shfl_xor_sync(0xffffffffu, a, off);
        b += __shfl_xor_sync(0xffffffffu, b, off);
    }
}
__device__ __forceinline__ void warpsum4(float& a, float& b, float& c, float& d) {
    #pragma unroll
    for (int off = 16; off > 0; off >>= 1) {
        a += __shfl_xor_sync(0xffffffffu, a, off);
        b += __shfl_xor_sync(0xffffffffu, b, off);
        c += __shfl_xor_sync(0xffffffffu, c, off);
        d += __shfl_xor_sync(0xffffffffu, d, off);
    }
}
__device__ __forceinline__ float blocksum256(float v, float* sh) {
    const int lane = threadIdx.x & 31;
    const int warp = threadIdx.x >> 5;
    float w = warpsum(v);
    if (lane == 0) sh[warp] = w;
    __syncthreads();
    float r = sh[0];
    #pragma unroll
    for (int i = 1; i < 8; i++) r += sh[i];
    return r;
}
__device__ __forceinline__ float acosh_over_s(float alpha) {
    float a2m1 = fmaf(alpha, alpha, -1.0f);
    float r = rsqrtf(a2m1);
    float s = a2m1 * r;
    return __logf(alpha + s) * r;
}

// ---------------------------------------------------------------------------
// Pass A: per-(chunk j, batch b) feature sums over 128 rows of S.
// ---------------------------------------------------------------------------
__global__ void __launch_bounds__(256) passA_kernel(const float* __restrict__ x) {
    const int j = blockIdx.x;
    const int b = blockIdx.y;
    const int d = threadIdx.x;
    const float* p = x + ((size_t)b*SEQ + (size_t)j*128) * DDIM + d;
    float a0=0.f,a1=0.f,a2=0.f,a3=0.f,a4=0.f,a5=0.f,a6=0.f,a7=0.f;
    #pragma unroll 2
    for (int s = 0; s < 128; s += 8) {
        a0 += p[(s+0)*DDIM]; a1 += p[(s+1)*DDIM];
        a2 += p[(s+2)*DDIM]; a3 += p[(s+3)*DDIM];
        a4 += p[(s+4)*DDIM]; a5 += p[(s+5)*DDIM];
        a6 += p[(s+6)*DDIM]; a7 += p[(s+7)*DDIM];
    }
    g_part[((size_t)(j*BATCH + b))*DDIM + d] = ((a0+a1)+(a2+a3)) + ((a4+a5)+(a6+a7));
}

// ---------------------------------------------------------------------------
__global__ void __launch_bounds__(256) a2a_kernel() {
    __shared__ float sh[8];
    const int b = blockIdx.x;
    const int d = threadIdx.x;
    float a = 0.f;
    #pragma unroll
    for (int j = 0; j < 8; j++)
        a += g_part[(size_t)(j*BATCH + b)*DDIM + d];
    a *= (1.0f / (float)SEQ);
    float p = (d == 0) ? -a*a : a*a;
    float l = blocksum256(p, sh);
    float dn = rsqrtf(fmaxf(fabsf(l), 1e-8f));
    g_cb[(size_t)b*DDIM + d] = a * dn;
}

__global__ void __launch_bounds__(256) a2b_kernel() {
    __shared__ float sh[8];
    const int d = threadIdx.x;
    float a = 0.f;
    #pragma unroll 8
    for (int b = 0; b < BATCH; b++) a += g_cb[(size_t)b*DDIM + d];
    a *= (1.0f / (float)BATCH);
    float p = (d == 0) ? -a*a : a*a;
    float l = blocksum256(p, sh);
    float dn = rsqrtf(fmaxf(fabsf(l), 1e-8f));
    float mv = a * dn;
    g_mean[d] = mv;
    if (d == 0) g_ic = 1.0f / (1.0f + mv);
}

// ---------------------------------------------------------------------------
// Pass B: warp-per-2-rows (idx, idx+HALF), descending. mean kept in SMEM
// (volatile reads) to cut 8 registers -> more resident warps. Also stores
// per-row scalars (f, gc, c) for pass C reuse.
// ---------------------------------------------------------------------------
__global__ void __launch_bounds__(256, 5) passB_kernel(const float* __restrict__ x) {
    __shared__ float sS[8][DDIM];
    __shared__ float sQ[8][DDIM];
    __shared__ __align__(16) float msv[DDIM];
    const int lane = threadIdx.x & 31;
    const int wib  = threadIdx.x >> 5;
    const int gw   = blockIdx.x * 8 + wib;
    const int nw   = NBLK_B * 8;

    if (threadIdx.x < 64)
        reinterpret_cast<float4*>(msv)[threadIdx.x] =
            reinterpret_cast<const float4*>(g_mean)[threadIdx.x];
    __syncthreads();
    volatile const float* mv = msv;

    const float m0 = g_mean[0];
    const float ic = g_ic;
    const int f0 = lane * 4;            // features f0..f0+3 (lo) and 128+f0.. (hi)

    float sm[8] = {0,0,0,0,0,0,0,0};
    float sq[8] = {0,0,0,0,0,0,0,0};

    for (int idx = gw; idx < HALF; idx += nw) {
        const int row = HALF - 1 - idx;
        const float4* rp1 = reinterpret_cast<const float4*>(x) + (size_t)row * 64;
        const float4* rp2 = rp1 + (size_t)HALF * 64;
        float a[8], b[8];
        {
            float4 v1 = rp1[lane], v2 = rp1[lane+32];
            float4 w1 = rp2[lane], w2 = rp2[lane+32];
            a[0]=v1.x; a[1]=v1.y; a[2]=v1.z; a[3]=v1.w;
            a[4]=v2.x; a[5]=v2.y; a[6]=v2.z; a[7]=v2.w;
            b[0]=w1.x; b[1]=w1.y; b[2]=w1.z; b[3]=w1.w;
            b[4]=w2.x; b[5]=w2.y; b[6]=w2.z; b[7]=w2.w;
        }
        float p1 = 0.f, p2 = 0.f;
        #pragma unroll
        for (int k = 0; k < 4; k++) {
            float mk = mv[f0 + k];
            if (k == 0 && lane == 0) { p1 -= mk*a[0]; p2 -= mk*b[0]; }
            else { p1 = fmaf(mk, a[k], p1); p2 = fmaf(mk, b[k], p2); }
        }
        #pragma unroll
        for (int k = 0; k < 4; k++) {
            float mk = mv[128 + f0 + k];
            p1 = fmaf(mk, a[4+k], p1);
            p2 = fmaf(mk, b[4+k], p2);
        }
        float x01 = __shfl_sync(0xffffffffu, a[0], 0);
        float x02 = __shfl_sync(0xffffffffu, b[0], 0);
        warpsum2(p1, p2);
        float al1 = fmaxf(-p1, 1.0f + 1e-7f);
        float al2 = fmaxf(-p2, 1.0f + 1e-7f);
        float f1 = acosh_over_s(al1);
        float f2 = acosh_over_s(al2);
        float c1 = f1 * (x01 - al1*m0) * ic;
        float c2 = f2 * (x02 - al2*m0) * ic;
        float gc1 = fmaf(f1, al1, c1);
        float gc2 = fmaf(f2, al2, c2);
        if (lane == 0) {
            g_rowsc[row]        = make_float4(f1, gc1, c1, 0.f);
            g_rowsc[row + HALF] = make_float4(f2, gc2, c2, 0.f);
        }
        #pragma unroll
        for (int k = 0; k < 4; k++) {
            float mk = mv[f0 + k];
            float t1 = fmaf(f1, a[k], -gc1*mk);
            float t2 = fmaf(f2, b[k], -gc2*mk);
            if (k == 0 && lane == 0) { t1 -= c1; t2 -= c2; }
            sm[k] += t1 + t2;
            sq[k] += fmaf(t1, t1, t2*t2);
        }
        #pragma unroll
        for (int k = 0; k < 4; k++) {
            float mk = mv[128 + f0 + k];
            float t1 = fmaf(f1, a[4+k], -gc1*mk);
            float t2 = fmaf(f2, b[4+k], -gc2*mk);
            sm[4+k] += t1 + t2;
            sq[4+k] += fmaf(t1, t1, t2*t2);
        }
    }

    __syncthreads();
    #pragma unroll
    for (int k = 0; k < 4; k++) {
        sS[wib][f0+k]     = sm[k];   sQ[wib][f0+k]     = sq[k];
        sS[wib][128+f0+k] = sm[4+k]; sQ[wib][128+f0+k] = sq[4+k];
    }
    __syncthreads();
    float accS = 0.f, accQ = 0.f;
    #pragma unroll
    for (int w = 0; w < 8; w++) { accS += sS[w][threadIdx.x]; accQ += sQ[w][threadIdx.x]; }
    g_bpS[(size_t)blockIdx.x*DDIM + threadIdx.x] = accS;
    g_bpQ[(size_t)blockIdx.x*DDIM + threadIdx.x] = accQ;
}

// ---------------------------------------------------------------------------
__global__ void __launch_bounds__(256) finB_kernel(const float* __restrict__ beta,
                                                   const float* __restrict__ gamma) {
    __shared__ float shS[8];
    __shared__ float shQ[8];
    const int d   = blockIdx.x;
    const int tid = threadIdx.x;
    const int lane = tid & 31;
    const int warp = tid >> 5;

    float s = 0.f, q = 0.f;
    #pragma unroll
    for (int i = 0; i < NBLK_B/256; i++) {
        int b = i*256 + tid;
        s += g_bpS[(size_t)b*DDIM + d];
        q += g_bpQ[(size_t)b*DDIM + d];
    }
    warpsum2(s, q);
    if (lane == 0) { shS[warp] = s; shQ[warp] = q; }
    __syncthreads();
    if (tid == 0) {
        float S = shS[0], Q = shQ[0];
        #pragma unroll
        for (int i = 1; i < 8; i++) { S += shS[i]; Q += shQ[i]; }
        const float invN = 1.0f / (float)NROWS;
        float mu  = S * invN;
        float var = Q * invN - mu*mu;
        g_scale[d] = gamma[0] * rsqrtf(var + 1e-5f);
        if (d == 0) {
            float b0 = beta[0];
            g_ib  = 1.0f / (1.0f + b0);
            g_lab = -2.0f * (1.0f + b0);
        }
    }
}

// ---------------------------------------------------------------------------
// Pass C: reuses per-row (f, gc, c). mean & scale in SMEM (volatile) to cut
// 16 registers; beta stays in registers (used 3x per row).
// ---------------------------------------------------------------------------
__global__ void __launch_bounds__(256) passC_kernel(const float* __restrict__ x,
                                                    const float* __restrict__ beta,
                                                    float* __restrict__ out) {
    __shared__ __align__(16) float msv[DDIM];
    __shared__ __align__(16) float scv[DDIM];
    const int lane = threadIdx.x & 31;
    const int gw   = (blockIdx.x * blockDim.x + threadIdx.x) >> 5;
    const int nw_  = (NBLK_C * 256) >> 5;

    if (threadIdx.x < 64) {
        reinterpret_cast<float4*>(msv)[threadIdx.x] =
            reinterpret_cast<const float4*>(g_mean)[threadIdx.x];
        reinterpret_cast<float4*>(scv)[threadIdx.x] =
            reinterpret_cast<const float4*>(g_scale)[threadIdx.x];
    }
    __syncthreads();
    volatile const float* mv = msv;
    volatile const float* sv = scv;

    float bt[8];
    {
        float4 v;
        v = reinterpret_cast<const float4*>(beta)[lane];    bt[0]=v.x; bt[1]=v.y; bt[2]=v.z; bt[3]=v.w;
        v = reinterpret_cast<const float4*>(beta)[lane+32]; bt[4]=v.x; bt[5]=v.y; bt[6]=v.z; bt[7]=v.w;
    }
    const float ib  = g_ib;
    const float lab = g_lab;
    const int f0 = lane * 4;

    for (int row = gw; row < HALF; row += nw_) {
        const float4* rp1 = reinterpret_cast<const float4*>(x) + (size_t)row * 64;
        const float4* rp2 = rp1 + (size_t)HALF * 64;
        float a[8], b[8];
        {
            float4 v1 = __ldcs(rp1 + lane), v2 = __ldcs(rp1 + lane + 32);
            float4 u1 = __ldcs(rp2 + lane), u2 = __ldcs(rp2 + lane + 32);
            a[0]=v1.x; a[1]=v1.y; a[2]=v1.z; a[3]=v1.w;
            a[4]=v2.x; a[5]=v2.y; a[6]=v2.z; a[7]=v2.w;
            b[0]=u1.x; b[1]=u1.y; b[2]=u1.z; b[3]=u1.w;
            b[4]=u2.x; b[5]=u2.y; b[6]=u2.z; b[7]=u2.w;
        }
        const float4 s1 = __ldg(&g_rowsc[row]);
        const float4 s2 = __ldg(&g_rowsc[row + HALF]);
        const float f1 = s1.x, gc1 = s1.y, c1 = s1.z;
        const float f2 = s2.x, gc2 = s2.y, c2 = s2.z;

        // w = t * scale
        #pragma unroll
        for (int k = 0; k < 4; k++) {
            float mk = mv[f0 + k];
            float sk = sv[f0 + k];
            float t1 = fmaf(f1, a[k], -gc1*mk);
            float t2 = fmaf(f2, b[k], -gc2*mk);
            if (k == 0 && lane == 0) { t1 -= c1; t2 -= c2; }
            a[k] = t1 * sk;
            b[k] = t2 * sk;
        }
        #pragma unroll
        for (int k = 0; k < 4; k++) {
            float mk = mv[128 + f0 + k];
            float sk = sv[128 + f0 + k];
            float t1 = fmaf(f1, a[4+k], -gc1*mk);
            float t2 = fmaf(f2, b[4+k], -gc2*mk);
            a[4+k] = t1 * sk;
            b[4+k] = t2 * sk;
        }
        float wt1 = __shfl_sync(0xffffffffu, a[0], 0);
        float wt2 = __shfl_sync(0xffffffffu, b[0], 0);

        // fused: q = linner(beta,w), n = linner(w,w)
        float q1 = bt[0]*a[0], q2 = bt[0]*b[0];
        float n1 = a[0]*a[0],  n2 = b[0]*b[0];
        if (lane == 0) { q1 = -q1; q2 = -q2; n1 = -n1; n2 = -n2; }
        #pragma unroll
        for (int k = 1; k < 8; k++) {
            q1 += bt[k]*a[k]; q2 += bt[k]*b[k];
            n1 += a[k]*a[k];  n2 += b[k]*b[k];
        }
        warpsum4(q1, n1, q2, n2);

        float cb1 = q1 * ib, cb2 = q2 * ib;
        float nn2_1 = n1 + 2.0f*cb1*(q1 - wt1) + cb1*cb1*lab;
        float nn2_2 = n2 + 2.0f*cb2*(q2 - wt2) + cb2*cb2*lab;
        float nn1 = sqrtf(fmaxf(nn2_1, 1e-7f));
        float nn2 = sqrtf(fmaxf(nn2_2, 1e-7f));
        float e1 = __expf(nn1), e2 = __expf(nn2);
        float ei1 = __frcp_rn(e1), ei2 = __frcp_rn(e2);
        float ch1 = 0.5f*(e1 + ei1), ch2 = 0.5f*(e2 + ei2);
        float sh1 = 0.5f*(e1 - ei1) * __frcp_rn(nn1);
        float sh2 = 0.5f*(e2 - ei2) * __frcp_rn(nn2);

        #pragma unroll
        for (int k = 0; k < 8; k++) {
            a[k] = fmaf(cb1, bt[k], a[k]);
            b[k] = fmaf(cb2, bt[k], b[k]);
            if (k == 0 && lane == 0) { a[0] += cb1; b[0] += cb2; }
        }

        float4* op1 = reinterpret_cast<float4*>(out) + (size_t)row * 64;
        float4* op2 = op1 + (size_t)HALF * 64;
        __stcs(op1 + lane,      make_float4(fmaf(ch1,bt[0],sh1*a[0]), fmaf(ch1,bt[1],sh1*a[1]),
                                            fmaf(ch1,bt[2],sh1*a[2]), fmaf(ch1,bt[3],sh1*a[3])));
        __stcs(op1 + lane + 32, make_float4(fmaf(ch1,bt[4],sh1*a[4]), fmaf(ch1,bt[5],sh1*a[5]),
                                            fmaf(ch1,bt[6],sh1*a[6]), fmaf(ch1,bt[7],sh1*a[7])));
        __stcs(op2 + lane,      make_float4(fmaf(ch2,bt[0],sh2*b[0]), fmaf(ch2,bt[1],sh2*b[1]),
                                            fmaf(ch2,bt[2],sh2*b[2]), fmaf(ch2,bt[3],sh2*b[3])));
        __stcs(op2 + lane + 32, make_float4(fmaf(ch2,bt[4],sh2*b[4]), fmaf(ch2,bt[5],sh2*b[5]),
                                            fmaf(ch2,bt[6],sh2*b[6]), fmaf(ch2,bt[7],sh2*b[7])));
    }
}

// ---------------------------------------------------------------------------
extern "C" void kernel_launch(void* const* d_in, const int* in_sizes, int n_in,
                              void* d_out, int out_size) {
    const float* x     = (const float*)d_in[0];
    const float* beta  = (const float*)d_in[1];
    const float* gamma = (const float*)d_in[2];
    float* out = (float*)d_out;

    dim3 gA(8, BATCH);
    passA_kernel<<<gA, 256>>>(x);
    a2a_kernel<<<BATCH, 256>>>();
    a2b_kernel<<<1, 256>>>();
    passB_kernel<<<NBLK_B, 256>>>(x);
    finB_kernel<<<DDIM, 256>>>(beta, gamma);
    passC_kernel<<<NBLK_C, 256>>>(x, beta, out);
}

// round 12
// speedup vs baseline: 1.3470x; 1.1521x over previous
#include <cuda_runtime.h>
#include <math.h>

#define DDIM   256
#define BATCH  128
#define SEQ    1024
#define NROWS  (BATCH*SEQ)          // 131072
#define HALF   (NROWS/2)            // 65536
#define NBLK_B 592                  // 148 SMs x 4 blocks: one full resident wave
#define NBLK_C 2048

// ---- scratch (static device globals; no allocation) ----
__device__ __align__(16) float g_part[8*BATCH*DDIM];
__device__ __align__(16) float g_cb[BATCH*DDIM];
__device__ __align__(16) float g_mean[DDIM];
__device__ float g_ic;
__device__ __align__(16) float g_bpS[NBLK_B*DDIM];
__device__ __align__(16) float g_bpQ[NBLK_B*DDIM];
__device__ __align__(16) float g_scale[DDIM];
__device__ float g_ib;
__device__ float g_lab;
__device__ __align__(16) float4 g_rowsc[NROWS];   // per-row (f, gc, c, 0)

__device__ __forceinline__ float warpsum(float v) {
    #pragma unroll
    for (int off = 16; off > 0; off >>= 1)
        v += __shfl_xor_sync(0xffffffffu, v, off);
    return v;
}
__device__ __forceinline__ void warpsum2(float& a, float& b) {
    #pragma unroll
    for (int off = 16; off > 0; off >>= 1) {
        a += __shfl_xor_sync(0xffffffffu, a, off);
        b += __shfl_xor_sync(0xffffffffu, b, off);
    }
}
__device__ __forceinline__ void warpsum4(float& a, float& b, float& c, float& d) {
    #pragma unroll
    for (int off = 16; off > 0; off >>= 1) {
        a += __shfl_xor_sync(0xffffffffu, a, off);
        b += __shfl_xor_sync(0xffffffffu, b, off);
        c += __shfl_xor_sync(0xffffffffu, c, off);
        d += __shfl_xor_sync(0xffffffffu, d, off);
    }
}
__device__ __forceinline__ float blocksum256(float v, float* sh) {
    const int lane = threadIdx.x & 31;
    const int warp = threadIdx.x >> 5;
    float w = warpsum(v);
    if (lane == 0) sh[warp] = w;
    __syncthreads();
    float r = sh[0];
    #pragma unroll
    for (int i = 1; i < 8; i++) r += sh[i];
    return r;
}
__device__ __forceinline__ float acosh_over_s(float alpha) {
    float a2m1 = fmaf(alpha, alpha, -1.0f);
    float r = rsqrtf(a2m1);
    float s = a2m1 * r;
    return __logf(alpha + s) * r;
}

// ---------------------------------------------------------------------------
// Pass A: per-(chunk j, batch b) feature sums over 128 rows of S.
// ---------------------------------------------------------------------------
__global__ void __launch_bounds__(256) passA_kernel(const float* __restrict__ x) {
    const int j = blockIdx.x;
    const int b = blockIdx.y;
    const int d = threadIdx.x;
    const float* p = x + ((size_t)b*SEQ + (size_t)j*128) * DDIM + d;
    float a0=0.f,a1=0.f,a2=0.f,a3=0.f,a4=0.f,a5=0.f,a6=0.f,a7=0.f;
    #pragma unroll 2
    for (int s = 0; s < 128; s += 8) {
        a0 += p[(s+0)*DDIM]; a1 += p[(s+1)*DDIM];
        a2 += p[(s+2)*DDIM]; a3 += p[(s+3)*DDIM];
        a4 += p[(s+4)*DDIM]; a5 += p[(s+5)*DDIM];
        a6 += p[(s+6)*DDIM]; a7 += p[(s+7)*DDIM];
    }
    g_part[((size_t)(j*BATCH + b))*DDIM + d] = ((a0+a1)+(a2+a3)) + ((a4+a5)+(a6+a7));
}

// ---------------------------------------------------------------------------
__global__ void __launch_bounds__(256) a2a_kernel() {
    __shared__ float sh[8];
    const int b = blockIdx.x;
    const int d = threadIdx.x;
    float a = 0.f;
    #pragma unroll
    for (int j = 0; j < 8; j++)
        a += g_part[(size_t)(j*BATCH + b)*DDIM + d];
    a *= (1.0f / (float)SEQ);
    float p = (d == 0) ? -a*a : a*a;
    float l = blocksum256(p, sh);
    float dn = rsqrtf(fmaxf(fabsf(l), 1e-8f));
    g_cb[(size_t)b*DDIM + d] = a * dn;
}

__global__ void __launch_bounds__(256) a2b_kernel() {
    __shared__ float sh[8];
    const int d = threadIdx.x;
    float a = 0.f;
    #pragma unroll 8
    for (int b = 0; b < BATCH; b++) a += g_cb[(size_t)b*DDIM + d];
    a *= (1.0f / (float)BATCH);
    float p = (d == 0) ? -a*a : a*a;
    float l = blocksum256(p, sh);
    float dn = rsqrtf(fmaxf(fabsf(l), 1e-8f));
    float mv = a * dn;
    g_mean[d] = mv;
    if (d == 0) g_ic = 1.0f / (1.0f + mv);
}

// ---------------------------------------------------------------------------
// Pass B: per-feature Sum(t), Sum(t^2); 2 rows/warp (idx, idx+HALF),
// descending. Stores per-row scalars (f, gc, c) for pass C reuse.
// ---------------------------------------------------------------------------
__global__ void __launch_bounds__(256) passB_kernel(const float* __restrict__ x) {
    __shared__ float sS[8][DDIM];
    __shared__ float sQ[8][DDIM];
    const int lane = threadIdx.x & 31;
    const int wib  = threadIdx.x >> 5;
    const int gw   = blockIdx.x * 8 + wib;
    const int nw   = NBLK_B * 8;

    float m[8];
    {
        float4 v;
        v = reinterpret_cast<const float4*>(g_mean)[lane];    m[0]=v.x; m[1]=v.y; m[2]=v.z; m[3]=v.w;
        v = reinterpret_cast<const float4*>(g_mean)[lane+32]; m[4]=v.x; m[5]=v.y; m[6]=v.z; m[7]=v.w;
    }
    const float m0 = g_mean[0];
    const float ic = g_ic;

    float sm[8] = {0,0,0,0,0,0,0,0};
    float sq[8] = {0,0,0,0,0,0,0,0};

    for (int idx = gw; idx < HALF; idx += nw) {
        const int row = HALF - 1 - idx;            // descending
        const float4* rp1 = reinterpret_cast<const float4*>(x) + (size_t)row * (DDIM/4);
        const float4* rp2 = rp1 + (size_t)HALF * (DDIM/4);
        float a[8], b[8];
        {
            float4 v1 = rp1[lane], v2 = rp1[lane+32];
            float4 w1 = rp2[lane], w2 = rp2[lane+32];
            a[0]=v1.x; a[1]=v1.y; a[2]=v1.z; a[3]=v1.w;
            a[4]=v2.x; a[5]=v2.y; a[6]=v2.z; a[7]=v2.w;
            b[0]=w1.x; b[1]=w1.y; b[2]=w1.z; b[3]=w1.w;
            b[4]=w2.x; b[5]=w2.y; b[6]=w2.z; b[7]=w2.w;
        }
        float p1 = m[0]*a[0], p2 = m[0]*b[0];
        if (lane == 0) { p1 = -p1; p2 = -p2; }
        #pragma unroll
        for (int k = 1; k < 8; k++) { p1 += m[k]*a[k]; p2 += m[k]*b[k]; }
        float x01 = __shfl_sync(0xffffffffu, a[0], 0);
        float x02 = __shfl_sync(0xffffffffu, b[0], 0);
        warpsum2(p1, p2);
        float al1 = fmaxf(-p1, 1.0f + 1e-7f);
        float al2 = fmaxf(-p2, 1.0f + 1e-7f);
        float f1 = acosh_over_s(al1);
        float f2 = acosh_over_s(al2);
        float c1 = f1 * (x01 - al1*m0) * ic;
        float c2 = f2 * (x02 - al2*m0) * ic;
        float gc1 = fmaf(f1, al1, c1);
        float gc2 = fmaf(f2, al2, c2);
        if (lane == 0) {
            g_rowsc[row]        = make_float4(f1, gc1, c1, 0.f);
            g_rowsc[row + HALF] = make_float4(f2, gc2, c2, 0.f);
        }
        #pragma unroll
        for (int k = 0; k < 8; k++) {
            float t1 = fmaf(f1, a[k], -gc1*m[k]);
            float t2 = fmaf(f2, b[k], -gc2*m[k]);
            if (k == 0 && lane == 0) { t1 -= c1; t2 -= c2; }
            sm[k] += t1 + t2;
            sq[k] += fmaf(t1, t1, t2*t2);
        }
    }

    const int d0i = lane * 4;
    #pragma unroll
    for (int k = 0; k < 4; k++) {
        sS[wib][d0i+k]     = sm[k];   sQ[wib][d0i+k]     = sq[k];
        sS[wib][128+d0i+k] = sm[4+k]; sQ[wib][128+d0i+k] = sq[4+k];
    }
    __syncthreads();
    float accS = 0.f, accQ = 0.f;
    #pragma unroll
    for (int w = 0; w < 8; w++) { accS += sS[w][threadIdx.x]; accQ += sQ[w][threadIdx.x]; }
    g_bpS[(size_t)blockIdx.x*DDIM + threadIdx.x] = accS;
    g_bpQ[(size_t)blockIdx.x*DDIM + threadIdx.x] = accQ;
}

// ---------------------------------------------------------------------------
// finB: fold partials -> scale[d]. grid 256 (feature per block); strided
// loop handles NBLK_B = 592.
// ---------------------------------------------------------------------------
__global__ void __launch_bounds__(256) finB_kernel(const float* __restrict__ beta,
                                                   const float* __restrict__ gamma) {
    __shared__ float shS[8];
    __shared__ float shQ[8];
    const int d   = blockIdx.x;
    const int tid = threadIdx.x;
    const int lane = tid & 31;
    const int warp = tid >> 5;

    float s = 0.f, q = 0.f;
    for (int b = tid; b < NBLK_B; b += 256) {
        s += g_bpS[(size_t)b*DDIM + d];
        q += g_bpQ[(size_t)b*DDIM + d];
    }
    warpsum2(s, q);
    if (lane == 0) { shS[warp] = s; shQ[warp] = q; }
    __syncthreads();
    if (tid == 0) {
        float S = shS[0], Q = shQ[0];
        #pragma unroll
        for (int i = 1; i < 8; i++) { S += shS[i]; Q += shQ[i]; }
        const float invN = 1.0f / (float)NROWS;
        float mu  = S * invN;
        float var = Q * invN - mu*mu;
        g_scale[d] = gamma[0] * rsqrtf(var + 1e-5f);
        if (d == 0) {
            float b0 = beta[0];
            g_ib  = 1.0f / (1.0f + b0);
            g_lab = -2.0f * (1.0f + b0);
        }
    }
}

// ---------------------------------------------------------------------------
// Pass C: reuses per-row (f, gc, c) from pass B — no dot/warpsum/acosh chain.
// ---------------------------------------------------------------------------
__global__ void __launch_bounds__(256) passC_kernel(const float* __restrict__ x,
                                                    const float* __restrict__ beta,
                                                    float* __restrict__ out) {
    const int lane = threadIdx.x & 31;
    const int gw   = (blockIdx.x * blockDim.x + threadIdx.x) >> 5;
    const int nw_  = (NBLK_C * 256) >> 5;   // 16384 warps

    float m[8], sc[8], bt[8];
    {
        float4 v;
        v = reinterpret_cast<const float4*>(g_mean)[lane];     m[0]=v.x; m[1]=v.y; m[2]=v.z; m[3]=v.w;
        v = reinterpret_cast<const float4*>(g_mean)[lane+32];  m[4]=v.x; m[5]=v.y; m[6]=v.z; m[7]=v.w;
        v = reinterpret_cast<const float4*>(g_scale)[lane];    sc[0]=v.x; sc[1]=v.y; sc[2]=v.z; sc[3]=v.w;
        v = reinterpret_cast<const float4*>(g_scale)[lane+32]; sc[4]=v.x; sc[5]=v.y; sc[6]=v.z; sc[7]=v.w;
        v = reinterpret_cast<const float4*>(beta)[lane];       bt[0]=v.x; bt[1]=v.y; bt[2]=v.z; bt[3]=v.w;
        v = reinterpret_cast<const float4*>(beta)[lane+32];    bt[4]=v.x; bt[5]=v.y; bt[6]=v.z; bt[7]=v.w;
    }
    const float ib  = g_ib;
    const float lab = g_lab;

    for (int row = gw; row < HALF; row += nw_) {
        const float4* rp1 = reinterpret_cast<const float4*>(x) + (size_t)row * (DDIM/4);
        const float4* rp2 = rp1 + (size_t)HALF * (DDIM/4);
        float a[8], b[8];
        {
            float4 v1 = __ldcs(rp1 + lane), v2 = __ldcs(rp1 + lane + 32);
            float4 u1 = __ldcs(rp2 + lane), u2 = __ldcs(rp2 + lane + 32);
            a[0]=v1.x; a[1]=v1.y; a[2]=v1.z; a[3]=v1.w;
            a[4]=v2.x; a[5]=v2.y; a[6]=v2.z; a[7]=v2.w;
            b[0]=u1.x; b[1]=u1.y; b[2]=u1.z; b[3]=u1.w;
            b[4]=u2.x; b[5]=u2.y; b[6]=u2.z; b[7]=u2.w;
        }
        const float4 s1 = __ldg(&g_rowsc[row]);
        const float4 s2 = __ldg(&g_rowsc[row + HALF]);
        const float f1 = s1.x, gc1 = s1.y, c1 = s1.z;
        const float f2 = s2.x, gc2 = s2.y, c2 = s2.z;

        // t scaled
        #pragma unroll
        for (int k = 0; k < 8; k++) {
            float t1 = fmaf(f1, a[k], -gc1*m[k]);
            float t2 = fmaf(f2, b[k], -gc2*m[k]);
            if (k == 0 && lane == 0) { t1 -= c1; t2 -= c2; }
            a[k] = t1 * sc[k];
            b[k] = t2 * sc[k];
        }
        float wt1 = __shfl_sync(0xffffffffu, a[0], 0);
        float wt2 = __shfl_sync(0xffffffffu, b[0], 0);

        // fused: q = linner(beta,w), n = linner(w,w)
        float q1 = bt[0]*a[0], q2 = bt[0]*b[0];
        float n1 = a[0]*a[0],  n2 = b[0]*b[0];
        if (lane == 0) { q1 = -q1; q2 = -q2; n1 = -n1; n2 = -n2; }
        #pragma unroll
        for (int k = 1; k < 8; k++) {
            q1 += bt[k]*a[k]; q2 += bt[k]*b[k];
            n1 += a[k]*a[k];  n2 += b[k]*b[k];
        }
        warpsum4(q1, n1, q2, n2);

        float cb1 = q1 * ib, cb2 = q2 * ib;
        float nn2_1 = n1 + 2.0f*cb1*(q1 - wt1) + cb1*cb1*lab;
        float nn2_2 = n2 + 2.0f*cb2*(q2 - wt2) + cb2*cb2*lab;
        float nn1 = sqrtf(fmaxf(nn2_1, 1e-7f));
        float nn2 = sqrtf(fmaxf(nn2_2, 1e-7f));
        float e1 = __expf(nn1), e2 = __expf(nn2);
        float ei1 = __frcp_rn(e1), ei2 = __frcp_rn(e2);
        float ch1 = 0.5f*(e1 + ei1), ch2 = 0.5f*(e2 + ei2);
        float sh1 = 0.5f*(e1 - ei1) * __frcp_rn(nn1);
        float sh2 = 0.5f*(e2 - ei2) * __frcp_rn(nn2);

        #pragma unroll
        for (int k = 0; k < 8; k++) {
            a[k] = fmaf(cb1, bt[k], a[k]);
            b[k] = fmaf(cb2, bt[k], b[k]);
            if (k == 0 && lane == 0) { a[0] += cb1; b[0] += cb2; }
        }

        float4* op1 = reinterpret_cast<float4*>(out) + (size_t)row * (DDIM/4);
        float4* op2 = op1 + (size_t)HALF * (DDIM/4);
        __stcs(op1 + lane,      make_float4(fmaf(ch1,bt[0],sh1*a[0]), fmaf(ch1,bt[1],sh1*a[1]),
                                            fmaf(ch1,bt[2],sh1*a[2]), fmaf(ch1,bt[3],sh1*a[3])));
        __stcs(op1 + lane + 32, make_float4(fmaf(ch1,bt[4],sh1*a[4]), fmaf(ch1,bt[5],sh1*a[5]),
                                            fmaf(ch1,bt[6],sh1*a[6]), fmaf(ch1,bt[7],sh1*a[7])));
        __stcs(op2 + lane,      make_float4(fmaf(ch2,bt[0],sh2*b[0]), fmaf(ch2,bt[1],sh2*b[1]),
                                            fmaf(ch2,bt[2],sh2*b[2]), fmaf(ch2,bt[3],sh2*b[3])));
        __stcs(op2 + lane + 32, make_float4(fmaf(ch2,bt[4],sh2*b[4]), fmaf(ch2,bt[5],sh2*b[5]),
                                            fmaf(ch2,bt[6],sh2*b[6]), fmaf(ch2,bt[7],sh2*b[7])));
    }
}

// ---------------------------------------------------------------------------
extern "C" void kernel_launch(void* const* d_in, const int* in_sizes, int n_in,
                              void* d_out, int out_size) {
    const float* x     = (const float*)d_in[0];
    const float* beta  = (const float*)d_in[1];
    const float* gamma = (const float*)d_in[2];
    float* out = (float*)d_out;

    dim3 gA(8, BATCH);
    passA_kernel<<<gA, 256>>>(x);
    a2a_kernel<<<BATCH, 256>>>();
    a2b_kernel<<<1, 256>>>();
    passB_kernel<<<NBLK_B, 256>>>(x);
    finB_kernel<<<DDIM, 256>>>(beta, gamma);
    passC_kernel<<<NBLK_C, 256>>>(x, beta, out);
}

// round 13
// speedup vs baseline: 1.4030x; 1.0415x over previous
#include <cuda_runtime.h>
#include <math.h>

#define DDIM   256
#define BATCH  128
#define SEQ    1024
#define NROWS  (BATCH*SEQ)          // 131072
#define HALF   (NROWS/2)            // 65536
#define NBLK_B 592                  // 148 SMs x 4 blocks: one full resident wave
#define NBLK_C 2048

// ---- scratch (static device globals; no allocation) ----
__device__ __align__(16) float g_part[8*BATCH*DDIM];
__device__ __align__(16) float g_cb[BATCH*DDIM];
__device__ __align__(16) float g_mean[DDIM];
__device__ float g_ic;
__device__ __align__(16) float g_bpS[NBLK_B*DDIM];
__device__ __align__(16) float g_bpQ[NBLK_B*DDIM];
__device__ __align__(16) float g_scale[DDIM];
__device__ float g_ib;
__device__ float g_lab;
__device__ __align__(16) float4 g_rowsc[NROWS];   // per-row (f, gc, c, 0)
__device__ unsigned int g_a2cnt;                   // zero-init; reset after use

__device__ __forceinline__ float warpsum(float v) {
    #pragma unroll
    for (int off = 16; off > 0; off >>= 1)
        v += __shfl_xor_sync(0xffffffffu, v, off);
    return v;
}
__device__ __forceinline__ void warpsum2(float& a, float& b) {
    #pragma unroll
    for (int off = 16; off > 0; off >>= 1) {
        a += __shfl_xor_sync(0xffffffffu, a, off);
        b += __shfl_xor_sync(0xffffffffu, b, off);
    }
}
__device__ __forceinline__ void warpsum4(float& a, float& b, float& c, float& d) {
    #pragma unroll
    for (int off = 16; off > 0; off >>= 1) {
        a += __shfl_xor_sync(0xffffffffu, a, off);
        b += __shfl_xor_sync(0xffffffffu, b, off);
        c += __shfl_xor_sync(0xffffffffu, c, off);
        d += __shfl_xor_sync(0xffffffffu, d, off);
    }
}
__device__ __forceinline__ float blocksum256(float v, float* sh) {
    const int lane = threadIdx.x & 31;
    const int warp = threadIdx.x >> 5;
    float w = warpsum(v);
    if (lane == 0) sh[warp] = w;
    __syncthreads();
    float r = sh[0];
    #pragma unroll
    for (int i = 1; i < 8; i++) r += sh[i];
    return r;
}
__device__ __forceinline__ float acosh_over_s(float alpha) {
    float a2m1 = fmaf(alpha, alpha, -1.0f);
    float r = rsqrtf(a2m1);
    float s = a2m1 * r;
    return __logf(alpha + s) * r;
}

// ---------------------------------------------------------------------------
// Pass A: per-(chunk j, batch b) feature sums over 128 rows of S.
// float4 layout: 256 thr = 64 float4-cols x 4 row-groups of 32 rows.
// ---------------------------------------------------------------------------
__global__ void __launch_bounds__(256) passA_kernel(const float* __restrict__ x) {
    __shared__ float red[4][DDIM];
    const int j    = blockIdx.x;
    const int b    = blockIdx.y;
    const int col4 = threadIdx.x & 63;
    const int rg   = threadIdx.x >> 6;      // 0..3
    const float4* p = reinterpret_cast<const float4*>(
        x + ((size_t)b*SEQ + (size_t)j*128) * DDIM) + (size_t)(rg*32) * 64 + col4;
    float4 acc = make_float4(0.f, 0.f, 0.f, 0.f);
    #pragma unroll 8
    for (int s = 0; s < 32; s++) {
        float4 v = p[(size_t)s * 64];
        acc.x += v.x; acc.y += v.y; acc.z += v.z; acc.w += v.w;
    }
    *reinterpret_cast<float4*>(&red[rg][col4*4]) = acc;
    __syncthreads();
    const int d = threadIdx.x;
    g_part[((size_t)(j*BATCH + b))*DDIM + d] =
        (red[0][d] + red[1][d]) + (red[2][d] + red[3][d]);
}

// ---------------------------------------------------------------------------
// A2 (fused): per-batch centroid (128 blocks); the LAST finishing block also
// performs the batch-level centroid -> g_mean, g_ic (saves one launch).
// ---------------------------------------------------------------------------
__global__ void __launch_bounds__(256) a2_kernel() {
    __shared__ float sh[8];
    __shared__ bool isLast;
    const int b = blockIdx.x;
    const int d = threadIdx.x;
    float a = 0.f;
    #pragma unroll
    for (int j = 0; j < 8; j++)
        a += g_part[(size_t)(j*BATCH + b)*DDIM + d];
    a *= (1.0f / (float)SEQ);
    float p = (d == 0) ? -a*a : a*a;
    float l = blocksum256(p, sh);
    float dn = rsqrtf(fmaxf(fabsf(l), 1e-8f));
    g_cb[(size_t)b*DDIM + d] = a * dn;

    __threadfence();
    if (d == 0) {
        unsigned int c = atomicAdd(&g_a2cnt, 1u);
        isLast = (c == BATCH - 1);
    }
    __syncthreads();
    if (isLast) {
        float s = 0.f;
        #pragma unroll 8
        for (int bb = 0; bb < BATCH; bb++) s += g_cb[(size_t)bb*DDIM + d];
        s *= (1.0f / (float)BATCH);
        float pp = (d == 0) ? -s*s : s*s;
        __syncthreads();
        float ll = blocksum256(pp, sh);
        float dn2 = rsqrtf(fmaxf(fabsf(ll), 1e-8f));
        float mv = s * dn2;
        g_mean[d] = mv;
        if (d == 0) { g_ic = 1.0f / (1.0f + mv); g_a2cnt = 0u; }
    }
}

// ---------------------------------------------------------------------------
// Pass B: per-feature Sum(t), Sum(t^2); 2 rows/warp (idx, idx+HALF),
// descending. Stores per-row scalars (f, gc, c) for pass C reuse.
// ---------------------------------------------------------------------------
__global__ void __launch_bounds__(256) passB_kernel(const float* __restrict__ x) {
    __shared__ float sS[8][DDIM];
    __shared__ float sQ[8][DDIM];
    const int lane = threadIdx.x & 31;
    const int wib  = threadIdx.x >> 5;
    const int gw   = blockIdx.x * 8 + wib;
    const int nw   = NBLK_B * 8;

    float m[8];
    {
        float4 v;
        v = reinterpret_cast<const float4*>(g_mean)[lane];    m[0]=v.x; m[1]=v.y; m[2]=v.z; m[3]=v.w;
        v = reinterpret_cast<const float4*>(g_mean)[lane+32]; m[4]=v.x; m[5]=v.y; m[6]=v.z; m[7]=v.w;
    }
    const float m0 = g_mean[0];
    const float ic = g_ic;

    float sm[8] = {0,0,0,0,0,0,0,0};
    float sq[8] = {0,0,0,0,0,0,0,0};

    for (int idx = gw; idx < HALF; idx += nw) {
        const int row = HALF - 1 - idx;            // descending
        const float4* rp1 = reinterpret_cast<const float4*>(x) + (size_t)row * (DDIM/4);
        const float4* rp2 = rp1 + (size_t)HALF * (DDIM/4);
        float a[8], b[8];
        {
            float4 v1 = rp1[lane], v2 = rp1[lane+32];
            float4 w1 = rp2[lane], w2 = rp2[lane+32];
            a[0]=v1.x; a[1]=v1.y; a[2]=v1.z; a[3]=v1.w;
            a[4]=v2.x; a[5]=v2.y; a[6]=v2.z; a[7]=v2.w;
            b[0]=w1.x; b[1]=w1.y; b[2]=w1.z; b[3]=w1.w;
            b[4]=w2.x; b[5]=w2.y; b[6]=w2.z; b[7]=w2.w;
        }
        float p1 = m[0]*a[0], p2 = m[0]*b[0];
        if (lane == 0) { p1 = -p1; p2 = -p2; }
        #pragma unroll
        for (int k = 1; k < 8; k++) { p1 += m[k]*a[k]; p2 += m[k]*b[k]; }
        float x01 = __shfl_sync(0xffffffffu, a[0], 0);
        float x02 = __shfl_sync(0xffffffffu, b[0], 0);
        warpsum2(p1, p2);
        float al1 = fmaxf(-p1, 1.0f + 1e-7f);
        float al2 = fmaxf(-p2, 1.0f + 1e-7f);
        float f1 = acosh_over_s(al1);
        float f2 = acosh_over_s(al2);
        float c1 = f1 * (x01 - al1*m0) * ic;
        float c2 = f2 * (x02 - al2*m0) * ic;
        float gc1 = fmaf(f1, al1, c1);
        float gc2 = fmaf(f2, al2, c2);
        if (lane == 0) {
            g_rowsc[row]        = make_float4(f1, gc1, c1, 0.f);
            g_rowsc[row + HALF] = make_float4(f2, gc2, c2, 0.f);
        }
        #pragma unroll
        for (int k = 0; k < 8; k++) {
            float t1 = fmaf(f1, a[k], -gc1*m[k]);
            float t2 = fmaf(f2, b[k], -gc2*m[k]);
            if (k == 0 && lane == 0) { t1 -= c1; t2 -= c2; }
            sm[k] += t1 + t2;
            sq[k] += fmaf(t1, t1, t2*t2);
        }
    }

    const int d0i = lane * 4;
    #pragma unroll
    for (int k = 0; k < 4; k++) {
        sS[wib][d0i+k]     = sm[k];   sQ[wib][d0i+k]     = sq[k];
        sS[wib][128+d0i+k] = sm[4+k]; sQ[wib][128+d0i+k] = sq[4+k];
    }
    __syncthreads();
    float accS = 0.f, accQ = 0.f;
    #pragma unroll
    for (int w = 0; w < 8; w++) { accS += sS[w][threadIdx.x]; accQ += sQ[w][threadIdx.x]; }
    g_bpS[(size_t)blockIdx.x*DDIM + threadIdx.x] = accS;
    g_bpQ[(size_t)blockIdx.x*DDIM + threadIdx.x] = accQ;
}

// ---------------------------------------------------------------------------
// finB: fold partials -> scale[d]. grid 256 (feature per block); strided
// loop handles NBLK_B = 592.
// ---------------------------------------------------------------------------
__global__ void __launch_bounds__(256) finB_kernel(const float* __restrict__ beta,
                                                   const float* __restrict__ gamma) {
    __shared__ float shS[8];
    __shared__ float shQ[8];
    const int d   = blockIdx.x;
    const int tid = threadIdx.x;
    const int lane = tid & 31;
    const int warp = tid >> 5;

    float s = 0.f, q = 0.f;
    for (int b = tid; b < NBLK_B; b += 256) {
        s += g_bpS[(size_t)b*DDIM + d];
        q += g_bpQ[(size_t)b*DDIM + d];
    }
    warpsum2(s, q);
    if (lane == 0) { shS[warp] = s; shQ[warp] = q; }
    __syncthreads();
    if (tid == 0) {
        float S = shS[0], Q = shQ[0];
        #pragma unroll
        for (int i = 1; i < 8; i++) { S += shS[i]; Q += shQ[i]; }
        const float invN = 1.0f / (float)NROWS;
        float mu  = S * invN;
        float var = Q * invN - mu*mu;
        g_scale[d] = gamma[0] * rsqrtf(var + 1e-5f);
        if (d == 0) {
            float b0 = beta[0];
            g_ib  = 1.0f / (1.0f + b0);
            g_lab = -2.0f * (1.0f + b0);
        }
    }
}

// ---------------------------------------------------------------------------
// Pass C: reuses per-row (f, gc, c) from pass B — no dot/warpsum/acosh chain.
// ---------------------------------------------------------------------------
__global__ void __launch_bounds__(256) passC_kernel(const float* __restrict__ x,
                                                    const float* __restrict__ beta,
                                                    float* __restrict__ out) {
    const int lane = threadIdx.x & 31;
    const int gw   = (blockIdx.x * blockDim.x + threadIdx.x) >> 5;
    const int nw_  = (NBLK_C * 256) >> 5;   // 16384 warps

    float m[8], sc[8], bt[8];
    {
        float4 v;
        v = reinterpret_cast<const float4*>(g_mean)[lane];     m[0]=v.x; m[1]=v.y; m[2]=v.z; m[3]=v.w;
        v = reinterpret_cast<const float4*>(g_mean)[lane+32];  m[4]=v.x; m[5]=v.y; m[6]=v.z; m[7]=v.w;
        v = reinterpret_cast<const float4*>(g_scale)[lane];    sc[0]=v.x; sc[1]=v.y; sc[2]=v.z; sc[3]=v.w;
        v = reinterpret_cast<const float4*>(g_scale)[lane+32]; sc[4]=v.x; sc[5]=v.y; sc[6]=v.z; sc[7]=v.w;
        v = reinterpret_cast<const float4*>(beta)[lane];       bt[0]=v.x; bt[1]=v.y; bt[2]=v.z; bt[3]=v.w;
        v = reinterpret_cast<const float4*>(beta)[lane+32];    bt[4]=v.x; bt[5]=v.y; bt[6]=v.z; bt[7]=v.w;
    }
    const float ib  = g_ib;
    const float lab = g_lab;

    for (int row = gw; row < HALF; row += nw_) {
        const float4* rp1 = reinterpret_cast<const float4*>(x) + (size_t)row * (DDIM/4);
        const float4* rp2 = rp1 + (size_t)HALF * (DDIM/4);
        float a[8], b[8];
        {
            float4 v1 = __ldcs(rp1 + lane), v2 = __ldcs(rp1 + lane + 32);
            float4 u1 = __ldcs(rp2 + lane), u2 = __ldcs(rp2 + lane + 32);
            a[0]=v1.x; a[1]=v1.y; a[2]=v1.z; a[3]=v1.w;
            a[4]=v2.x; a[5]=v2.y; a[6]=v2.z; a[7]=v2.w;
            b[0]=u1.x; b[1]=u1.y; b[2]=u1.z; b[3]=u1.w;
            b[4]=u2.x; b[5]=u2.y; b[6]=u2.z; b[7]=u2.w;
        }
        const float4 s1 = __ldg(&g_rowsc[row]);
        const float4 s2 = __ldg(&g_rowsc[row + HALF]);
        const float f1 = s1.x, gc1 = s1.y, c1 = s1.z;
        const float f2 = s2.x, gc2 = s2.y, c2 = s2.z;

        // t scaled
        #pragma unroll
        for (int k = 0; k < 8; k++) {
            float t1 = fmaf(f1, a[k], -gc1*m[k]);
            float t2 = fmaf(f2, b[k], -gc2*m[k]);
            if (k == 0 && lane == 0) { t1 -= c1; t2 -= c2; }
            a[k] = t1 * sc[k];
            b[k] = t2 * sc[k];
        }
        float wt1 = __shfl_sync(0xffffffffu, a[0], 0);
        float wt2 = __shfl_sync(0xffffffffu, b[0], 0);

        // fused: q = linner(beta,w), n = linner(w,w)
        float q1 = bt[0]*a[0], q2 = bt[0]*b[0];
        float n1 = a[0]*a[0],  n2 = b[0]*b[0];
        if (lane == 0) { q1 = -q1; q2 = -q2; n1 = -n1; n2 = -n2; }
        #pragma unroll
        for (int k = 1; k < 8; k++) {
            q1 += bt[k]*a[k]; q2 += bt[k]*b[k];
            n1 += a[k]*a[k];  n2 += b[k]*b[k];
        }
        warpsum4(q1, n1, q2, n2);

        float cb1 = q1 * ib, cb2 = q2 * ib;
        float nn2_1 = n1 + 2.0f*cb1*(q1 - wt1) + cb1*cb1*lab;
        float nn2_2 = n2 + 2.0f*cb2*(q2 - wt2) + cb2*cb2*lab;
        float nn1 = sqrtf(fmaxf(nn2_1, 1e-7f));
        float nn2 = sqrtf(fmaxf(nn2_2, 1e-7f));
        float e1 = __expf(nn1), e2 = __expf(nn2);
        float ei1 = __frcp_rn(e1), ei2 = __frcp_rn(e2);
        float ch1 = 0.5f*(e1 + ei1), ch2 = 0.5f*(e2 + ei2);
        float sh1 = 0.5f*(e1 - ei1) * __frcp_rn(nn1);
        float sh2 = 0.5f*(e2 - ei2) * __frcp_rn(nn2);

        #pragma unroll
        for (int k = 0; k < 8; k++) {
            a[k] = fmaf(cb1, bt[k], a[k]);
            b[k] = fmaf(cb2, bt[k], b[k]);
            if (k == 0 && lane == 0) { a[0] += cb1; b[0] += cb2; }
        }

        float4* op1 = reinterpret_cast<float4*>(out) + (size_t)row * (DDIM/4);
        float4* op2 = op1 + (size_t)HALF * (DDIM/4);
        __stcs(op1 + lane,      make_float4(fmaf(ch1,bt[0],sh1*a[0]), fmaf(ch1,bt[1],sh1*a[1]),
                                            fmaf(ch1,bt[2],sh1*a[2]), fmaf(ch1,bt[3],sh1*a[3])));
        __stcs(op1 + lane + 32, make_float4(fmaf(ch1,bt[4],sh1*a[4]), fmaf(ch1,bt[5],sh1*a[5]),
                                            fmaf(ch1,bt[6],sh1*a[6]), fmaf(ch1,bt[7],sh1*a[7])));
        __stcs(op2 + lane,      make_float4(fmaf(ch2,bt[0],sh2*b[0]), fmaf(ch2,bt[1],sh2*b[1]),
                                            fmaf(ch2,bt[2],sh2*b[2]), fmaf(ch2,bt[3],sh2*b[3])));
        __stcs(op2 + lane + 32, make_float4(fmaf(ch2,bt[4],sh2*b[4]), fmaf(ch2,bt[5],sh2*b[5]),
                                            fmaf(ch2,bt[6],sh2*b[6]), fmaf(ch2,bt[7],sh2*b[7])));
    }
}

// ---------------------------------------------------------------------------
extern "C" void kernel_launch(void* const* d_in, const int* in_sizes, int n_in,
                              void* d_out, int out_size) {
    const float* x     = (const float*)d_in[0];
    const float* beta  = (const float*)d_in[1];
    const float* gamma = (const float*)d_in[2];
    float* out = (float*)d_out;

    dim3 gA(8, BATCH);
    passA_kernel<<<gA, 256>>>(x);
    a2_kernel<<<BATCH, 256>>>();
    passB_kernel<<<NBLK_B, 256>>>(x);
    finB_kernel<<<DDIM, 256>>>(beta, gamma);
    passC_kernel<<<NBLK_C, 256>>>(x, beta, out);
}